// round 1
// baseline (speedup 1.0000x reference)
#include <cuda_runtime.h>
#include <cstdint>

#define T_SEQ  2048
#define BATCH  8
#define DMODEL 1024
#define WIN    64
#define CLUSTER 4
#define DPC    256   // dims per CTA in scan cluster

// 64 MB scratch for q_local = feature @ wq_w + wq_b
__device__ float g_q[(size_t)BATCH * T_SEQ * DMODEL];

// ---------------------------------------------------------------------------
// GEMM: q = feature(16384x1024) @ wq(1024x1024) + bias   (fp32 SIMT, 128x128x16)
// ---------------------------------------------------------------------------
#define BM 128
#define BN 128
#define BK 16

__global__ __launch_bounds__(256) void gemm_kernel(
    const float* __restrict__ A, const float* __restrict__ Bw,
    const float* __restrict__ bias)
{
    __shared__ __align__(16) float As[BK][BM];
    __shared__ __align__(16) float Bs[BK][BN];
    const int tid = threadIdx.x;
    const int m0 = blockIdx.x * BM;
    const int n0 = blockIdx.y * BN;
    const int ty = tid >> 4;   // 0..15
    const int tx = tid & 15;   // 0..15

    float acc[8][8];
#pragma unroll
    for (int i = 0; i < 8; i++)
#pragma unroll
        for (int j = 0; j < 8; j++) acc[i][j] = 0.f;

    for (int k0 = 0; k0 < DMODEL; k0 += BK) {
#pragma unroll
        for (int i = 0; i < 2; i++) {
            int s = tid + i * 256;
            int r = s >> 2;            // 0..127
            int c = (s & 3) << 2;      // 0,4,8,12
            float4 a = *(const float4*)(A + (size_t)(m0 + r) * DMODEL + k0 + c);
            As[c + 0][r] = a.x; As[c + 1][r] = a.y;
            As[c + 2][r] = a.z; As[c + 3][r] = a.w;
        }
#pragma unroll
        for (int i = 0; i < 2; i++) {
            int s = tid + i * 256;
            int r = s >> 5;            // 0..15
            int c = (s & 31) << 2;     // 0..124
            *(float4*)&Bs[r][c] = *(const float4*)(Bw + (size_t)(k0 + r) * DMODEL + n0 + c);
        }
        __syncthreads();
#pragma unroll
        for (int k = 0; k < BK; k++) {
            float a[8], b[8];
            *(float4*)&a[0] = *(float4*)&As[k][ty * 8];
            *(float4*)&a[4] = *(float4*)&As[k][ty * 8 + 4];
            *(float4*)&b[0] = *(float4*)&Bs[k][tx * 8];
            *(float4*)&b[4] = *(float4*)&Bs[k][tx * 8 + 4];
#pragma unroll
            for (int i = 0; i < 8; i++)
#pragma unroll
                for (int j = 0; j < 8; j++)
                    acc[i][j] = fmaf(a[i], b[j], acc[i][j]);
        }
        __syncthreads();
    }

    float bb[8];
    *(float4*)&bb[0] = *(const float4*)(bias + n0 + tx * 8);
    *(float4*)&bb[4] = *(const float4*)(bias + n0 + tx * 8 + 4);
#pragma unroll
    for (int i = 0; i < 8; i++) {
        float* cp = g_q + (size_t)(m0 + ty * 8 + i) * DMODEL + n0 + tx * 8;
        float4 o0 = make_float4(acc[i][0] + bb[0], acc[i][1] + bb[1],
                                acc[i][2] + bb[2], acc[i][3] + bb[3]);
        float4 o1 = make_float4(acc[i][4] + bb[4], acc[i][5] + bb[5],
                                acc[i][6] + bb[6], acc[i][7] + bb[7]);
        *(float4*)cp = o0;
        *(float4*)(cp + 4) = o1;
    }
}

// ---------------------------------------------------------------------------
// Scan: cluster of 4 CTAs per batch. Each CTA holds a 64x256 slice of the ring
// buffer in registers (warp w owns physical rows 8w..8w+7; lane owns 8 dims).
// Per step: local partial scores -> DSMEM broadcast -> cluster barrier ->
// softmax -> local weighted sum -> cross-warp reduce -> ring append.
// ---------------------------------------------------------------------------
__device__ __forceinline__ uint32_t cvta_sh(const void* p) {
    return (uint32_t)__cvta_generic_to_shared(p);
}
__device__ __forceinline__ uint32_t mapa_sh(uint32_t addr, uint32_t rank) {
    uint32_t r;
    asm("mapa.shared::cluster.u32 %0, %1, %2;" : "=r"(r) : "r"(addr), "r"(rank));
    return r;
}
__device__ __forceinline__ void st_cluster_f32(uint32_t addr, float v) {
    asm volatile("st.shared::cluster.f32 [%0], %1;" :: "r"(addr), "f"(v) : "memory");
}
__device__ __forceinline__ void cluster_sync_all() {
    asm volatile("barrier.cluster.arrive.aligned;" ::: "memory");
    asm volatile("barrier.cluster.wait.aligned;" ::: "memory");
}

__global__ void __cluster_dims__(CLUSTER, 1, 1) __launch_bounds__(256, 1)
scan_kernel(const float* __restrict__ feature, const float* __restrict__ w2w,
            const float* __restrict__ w2b, float* __restrict__ vout)
{
    __shared__ __align__(16) float ps[2][CLUSTER][WIN];  // partial scores, double-buffered
    __shared__ __align__(16) float alpha_sh[WIN];
    __shared__ __align__(16) float pv[8][DPC];           // per-warp partial v
    __shared__ __align__(16) float v_sh[DPC];

    const int rank = blockIdx.x & (CLUSTER - 1);
    const int b    = blockIdx.x / CLUSTER;
    const int tid  = threadIdx.x;
    const int warp = tid >> 5;
    const int lane = tid & 31;
    const int d0   = rank * DPC + lane * 8;   // this lane's first global dim

    // w2 slice for this lane
    float w2v[8];
    *(float4*)&w2v[0] = *(const float4*)(w2w + d0);
    *(float4*)&w2v[4] = *(const float4*)(w2w + d0 + 4);
    const float bias2 = w2b[0];

    // ring buffer in registers: buf[r][k] = x_{row}[d0+k], row = warp*8+r
    float buf[8][8];
#pragma unroll
    for (int r = 0; r < 8; r++) {
        const float* fp = feature + ((size_t)b * T_SEQ + (warp * 8 + r)) * DMODEL + d0;
        float4 x0 = *(const float4*)fp;
        float4 x1 = *(const float4*)(fp + 4);
        buf[r][0] = x0.x; buf[r][1] = x0.y; buf[r][2] = x0.z; buf[r][3] = x0.w;
        buf[r][4] = x1.x; buf[r][5] = x1.y; buf[r][6] = x1.z; buf[r][7] = x1.w;
    }

    const uint32_t ps_base = cvta_sh(&ps[0][0][0]);

    for (int t = WIN; t < T_SEQ; ++t) {
        const int slot = t & 1;

        // qw = q_local[b][t][d0..] * w2
        const float* qp = g_q + ((size_t)b * T_SEQ + t) * DMODEL + d0;
        float4 q0 = *(const float4*)qp;
        float4 q1 = *(const float4*)(qp + 4);
        float qw[8];
        qw[0] = q0.x * w2v[0]; qw[1] = q0.y * w2v[1];
        qw[2] = q0.z * w2v[2]; qw[3] = q0.w * w2v[3];
        qw[4] = q1.x * w2v[4]; qw[5] = q1.y * w2v[5];
        qw[6] = q1.z * w2v[6]; qw[7] = q1.w * w2v[7];

        // pass 1: partial scores for this warp's 8 rows over this CTA's 256 dims
        float myScore = 0.f;
#pragma unroll
        for (int r = 0; r < 8; r++) {
            float s = qw[0] * buf[r][0];
#pragma unroll
            for (int k = 1; k < 8; k++) s = fmaf(qw[k], buf[r][k], s);
            s += __shfl_xor_sync(0xffffffffu, s, 16);
            s += __shfl_xor_sync(0xffffffffu, s, 8);
            s += __shfl_xor_sync(0xffffffffu, s, 4);
            s += __shfl_xor_sync(0xffffffffu, s, 2);
            s += __shfl_xor_sync(0xffffffffu, s, 1);
            if (lane == r) myScore = s;
        }
        // lanes 0..7: broadcast partial score of row warp*8+lane to all 4 CTAs
        if (lane < 8) {
            uint32_t laddr = ps_base +
                (uint32_t)(((slot * CLUSTER + rank) * WIN) + (warp * 8 + lane)) * 4u;
#pragma unroll
            for (int c = 0; c < CLUSTER; c++)
                st_cluster_f32(mapa_sh(laddr, c), myScore);
        }

        cluster_sync_all();

        // warp 0: combine partials, softmax over 64 rows + zero-row bias term
        if (warp == 0) {
            float sa = ps[slot][0][lane] + ps[slot][1][lane] +
                       ps[slot][2][lane] + ps[slot][3][lane];
            float sb = ps[slot][0][lane + 32] + ps[slot][1][lane + 32] +
                       ps[slot][2][lane + 32] + ps[slot][3][lane + 32];
            float m = fmaxf(sa, sb);
#pragma unroll
            for (int o = 16; o > 0; o >>= 1)
                m = fmaxf(m, __shfl_xor_sync(0xffffffffu, m, o));
            m = fmaxf(m, bias2);
            float ea = __expf(sa - m);
            float eb = __expf(sb - m);
            float sum = ea + eb + ((lane == 0) ? __expf(bias2 - m) : 0.f);
#pragma unroll
            for (int o = 16; o > 0; o >>= 1)
                sum += __shfl_xor_sync(0xffffffffu, sum, o);
            float inv = 1.f / sum;
            alpha_sh[lane]      = ea * inv;
            alpha_sh[lane + 32] = eb * inv;
        }
        __syncthreads();

        // pass 2: partial v over this warp's rows
        float vp[8] = {0.f, 0.f, 0.f, 0.f, 0.f, 0.f, 0.f, 0.f};
#pragma unroll
        for (int r = 0; r < 8; r++) {
            float a = alpha_sh[warp * 8 + r];
#pragma unroll
            for (int k = 0; k < 8; k++) vp[k] = fmaf(a, buf[r][k], vp[k]);
        }
        *(float4*)&pv[warp][lane * 8]     = make_float4(vp[0], vp[1], vp[2], vp[3]);
        *(float4*)&pv[warp][lane * 8 + 4] = make_float4(vp[4], vp[5], vp[6], vp[7]);
        __syncthreads();

        // reduce partial v across 8 warps; write v to d_out (scratch for LN)
        float v = pv[0][tid] + pv[1][tid] + pv[2][tid] + pv[3][tid] +
                  pv[4][tid] + pv[5][tid] + pv[6][tid] + pv[7][tid];
        v_sh[tid] = v;
        vout[((size_t)b * T_SEQ + t) * DMODEL + rank * DPC + tid] = v;
        __syncthreads();

        // ring append: physical slot t%64 gets v
        const int prow = t & (WIN - 1);
        if (warp == (prow >> 3)) {
            const int rr = prow & 7;
            float4 n0 = *(float4*)&v_sh[lane * 8];
            float4 n1 = *(float4*)&v_sh[lane * 8 + 4];
#define SET_ROW(R) \
    buf[R][0] = n0.x; buf[R][1] = n0.y; buf[R][2] = n0.z; buf[R][3] = n0.w; \
    buf[R][4] = n1.x; buf[R][5] = n1.y; buf[R][6] = n1.z; buf[R][7] = n1.w;
            switch (rr) {
                case 0: { SET_ROW(0) } break;
                case 1: { SET_ROW(1) } break;
                case 2: { SET_ROW(2) } break;
                case 3: { SET_ROW(3) } break;
                case 4: { SET_ROW(4) } break;
                case 5: { SET_ROW(5) } break;
                case 6: { SET_ROW(6) } break;
                case 7: { SET_ROW(7) } break;
            }
#undef SET_ROW
        }
        // next iteration's cluster_sync orders reuse of v_sh / alpha_sh / ps slots
    }
}

// ---------------------------------------------------------------------------
// Epilogue: y = tanh(v)*f + f, then LayerNorm. One CTA (256 thr) per row.
// v comes from d_out for t>=64 (written by scan), from feature for t<64.
// ---------------------------------------------------------------------------
__global__ __launch_bounds__(256) void ln_kernel(
    const float* __restrict__ feature, const float* __restrict__ g,
    const float* __restrict__ bt, float* __restrict__ out)
{
    const int row = blockIdx.x;               // 0..16383
    const int t = row & (T_SEQ - 1);
    const float* fp = feature + (size_t)row * DMODEL;
    float* op = out + (size_t)row * DMODEL;
    const float* vp = (t < WIN) ? fp : op;
    const int tid = threadIdx.x;
    const int lane = tid & 31, warp = tid >> 5;

    float4 f = *(const float4*)(fp + tid * 4);
    float4 v = *(const float4*)(vp + tid * 4);
    float y0 = tanhf(v.x) * f.x + f.x;
    float y1 = tanhf(v.y) * f.y + f.y;
    float y2 = tanhf(v.z) * f.z + f.z;
    float y3 = tanhf(v.w) * f.w + f.w;

    float s  = y0 + y1 + y2 + y3;
    float ss = y0 * y0 + y1 * y1 + y2 * y2 + y3 * y3;
#pragma unroll
    for (int o = 16; o > 0; o >>= 1) {
        s  += __shfl_xor_sync(0xffffffffu, s, o);
        ss += __shfl_xor_sync(0xffffffffu, ss, o);
    }
    __shared__ float red[8][2];
    if (lane == 0) { red[warp][0] = s; red[warp][1] = ss; }
    __syncthreads();
    if (warp == 0) {
        float a = (lane < 8) ? red[lane][0] : 0.f;
        float c = (lane < 8) ? red[lane][1] : 0.f;
#pragma unroll
        for (int o = 4; o > 0; o >>= 1) {
            a += __shfl_xor_sync(0xffffffffu, a, o);
            c += __shfl_xor_sync(0xffffffffu, c, o);
        }
        if (lane == 0) { red[0][0] = a; red[0][1] = c; }
    }
    __syncthreads();
    const float mu   = red[0][0] * (1.f / DMODEL);
    const float var  = red[0][1] * (1.f / DMODEL) - mu * mu;
    const float rstd = rsqrtf(var + 1e-5f);

    float4 gg = *(const float4*)(g + tid * 4);
    float4 bb = *(const float4*)(bt + tid * 4);
    float4 o;
    o.x = (y0 - mu) * rstd * gg.x + bb.x;
    o.y = (y1 - mu) * rstd * gg.y + bb.y;
    o.z = (y2 - mu) * rstd * gg.z + bb.z;
    o.w = (y3 - mu) * rstd * gg.w + bb.w;
    *(float4*)(op + tid * 4) = o;
}

// ---------------------------------------------------------------------------
extern "C" void kernel_launch(void* const* d_in, const int* in_sizes, int n_in,
                              void* d_out, int out_size)
{
    const float* feature = (const float*)d_in[0];
    const float* wq_w    = (const float*)d_in[1];
    const float* wq_b    = (const float*)d_in[2];
    const float* w2_w    = (const float*)d_in[3];
    const float* w2_b    = (const float*)d_in[4];
    const float* ln_g    = (const float*)d_in[5];
    const float* ln_b    = (const float*)d_in[6];
    float* out = (float*)d_out;

    dim3 ggrid((BATCH * T_SEQ) / BM, DMODEL / BN);  // (128, 8)
    gemm_kernel<<<ggrid, 256>>>(feature, wq_w, wq_b);
    scan_kernel<<<BATCH * CLUSTER, 256>>>(feature, w2_w, w2_b, out);
    ln_kernel<<<BATCH * T_SEQ, 256>>>(feature, ln_g, ln_b, out);
}

// round 2
// speedup vs baseline: 2.7888x; 2.7888x over previous
#include <cuda_runtime.h>
#include <cstdint>

#define T_SEQ  2048
#define BATCH  8
#define DMODEL 1024
#define WIN    64

// Scratch (≈10 MB total)
__device__ float g_M[(size_t)BATCH * DMODEL * WIN];   // M[b][d][j] = sum_e wq[d,e] w2[e] F[b,j,e]
__device__ float g_P[(size_t)BATCH * T_SEQ * WIN];    // p_t[j] per batch
__device__ float g_C[(size_t)BATCH * T_SEQ * WIN];    // coefficients of v_t
__device__ float g_bP[BATCH * WIN];                   // bias term of p

// ---------------------------------------------------------------------------
// biasP[b][j] = sum_e wq_b[e] * w2[e] * F[b][j][e]
// ---------------------------------------------------------------------------
__global__ __launch_bounds__(256) void bias_p_kernel(
    const float* __restrict__ feat, const float* __restrict__ wqb,
    const float* __restrict__ w2)
{
    const int b = blockIdx.x;
    const int j = threadIdx.x >> 2;
    const int q = threadIdx.x & 3;
    const float* fp = feat + ((size_t)b * T_SEQ + j) * DMODEL + q * 256;
    float s = 0.f;
#pragma unroll 4
    for (int e = 0; e < 256; e += 4) {
        float4 f  = *(const float4*)(fp + e);
        float4 wb = *(const float4*)(wqb + q * 256 + e);
        float4 ww = *(const float4*)(w2 + q * 256 + e);
        s += f.x * wb.x * ww.x + f.y * wb.y * ww.y +
             f.z * wb.z * ww.z + f.w * wb.w * ww.w;
    }
    s += __shfl_xor_sync(0xffffffffu, s, 1);
    s += __shfl_xor_sync(0xffffffffu, s, 2);
    if (q == 0) g_bP[b * WIN + j] = s;
}

// ---------------------------------------------------------------------------
// k1: M[b] = wq (1024x1024) @ G^T, G[j,e] = F[b,j,e]*w2[e].  Tile 128x64, K=1024.
// grid (8 dblocks, 8 batches), 256 threads.
// ---------------------------------------------------------------------------
__global__ __launch_bounds__(256) void m_kernel(
    const float* __restrict__ wq, const float* __restrict__ w2,
    const float* __restrict__ feat)
{
    __shared__ float As[16][129];   // As[k][r] = wq[d0+r][e0+k]
    __shared__ float Bs[16][68];    // Bs[k][j] = F[b][j][e0+k]*w2[e0+k]
    const int b  = blockIdx.y;
    const int d0 = blockIdx.x * 128;
    const int tid = threadIdx.x;
    const int ty = tid >> 3, tx = tid & 7;
    const int r0 = ty * 4, j0 = tx * 8;

    float acc[4][8];
#pragma unroll
    for (int i = 0; i < 4; i++)
#pragma unroll
        for (int j = 0; j < 8; j++) acc[i][j] = 0.f;

    for (int e0 = 0; e0 < DMODEL; e0 += 16) {
#pragma unroll
        for (int l = 0; l < 2; l++) {
            int s = tid + l * 256;
            int r = s >> 2, kc = (s & 3) * 4;
            float4 w = *(const float4*)(wq + (size_t)(d0 + r) * DMODEL + e0 + kc);
            As[kc + 0][r] = w.x; As[kc + 1][r] = w.y;
            As[kc + 2][r] = w.z; As[kc + 3][r] = w.w;
        }
        {
            int j = tid >> 2, kc = (tid & 3) * 4;
            float4 f = *(const float4*)(feat + ((size_t)b * T_SEQ + j) * DMODEL + e0 + kc);
            float4 w = *(const float4*)(w2 + e0 + kc);
            Bs[kc + 0][j] = f.x * w.x; Bs[kc + 1][j] = f.y * w.y;
            Bs[kc + 2][j] = f.z * w.z; Bs[kc + 3][j] = f.w * w.w;
        }
        __syncthreads();
#pragma unroll
        for (int k = 0; k < 16; k++) {
            float a[4], bb[8];
            a[0] = As[k][r0]; a[1] = As[k][r0 + 1];
            a[2] = As[k][r0 + 2]; a[3] = As[k][r0 + 3];
            *(float4*)&bb[0] = *(float4*)&Bs[k][j0];
            *(float4*)&bb[4] = *(float4*)&Bs[k][j0 + 4];
#pragma unroll
            for (int i = 0; i < 4; i++)
#pragma unroll
                for (int j = 0; j < 8; j++)
                    acc[i][j] = fmaf(a[i], bb[j], acc[i][j]);
        }
        __syncthreads();
    }
#pragma unroll
    for (int i = 0; i < 4; i++) {
        float* mp = g_M + ((size_t)b * DMODEL + d0 + r0 + i) * WIN + j0;
        *(float4*)mp       = make_float4(acc[i][0], acc[i][1], acc[i][2], acc[i][3]);
        *(float4*)(mp + 4) = make_float4(acc[i][4], acc[i][5], acc[i][6], acc[i][7]);
    }
}

// ---------------------------------------------------------------------------
// k2: P[b] = feature[b] (2048x1024) @ M[b] (1024x64) + biasP.  Tile 128x64.
// grid (16 tblocks, 8 batches), 256 threads.
// ---------------------------------------------------------------------------
__global__ __launch_bounds__(256) void p_kernel(const float* __restrict__ feat)
{
    __shared__ float As[16][129];
    __shared__ float Bs[16][68];
    const int b  = blockIdx.y;
    const int t0 = blockIdx.x * 128;
    const int tid = threadIdx.x;
    const int ty = tid >> 3, tx = tid & 7;
    const int r0 = ty * 4, j0 = tx * 8;

    float acc[4][8];
#pragma unroll
    for (int i = 0; i < 4; i++)
#pragma unroll
        for (int j = 0; j < 8; j++) acc[i][j] = 0.f;

    for (int e0 = 0; e0 < DMODEL; e0 += 16) {
#pragma unroll
        for (int l = 0; l < 2; l++) {
            int s = tid + l * 256;
            int r = s >> 2, kc = (s & 3) * 4;
            float4 w = *(const float4*)(feat + ((size_t)b * T_SEQ + t0 + r) * DMODEL + e0 + kc);
            As[kc + 0][r] = w.x; As[kc + 1][r] = w.y;
            As[kc + 2][r] = w.z; As[kc + 3][r] = w.w;
        }
        {
            int k = tid >> 4, j4 = (tid & 15) * 4;
            *(float4*)&Bs[k][j4] =
                *(const float4*)(g_M + ((size_t)b * DMODEL + e0 + k) * WIN + j4);
        }
        __syncthreads();
#pragma unroll
        for (int k = 0; k < 16; k++) {
            float a[4], bb[8];
            a[0] = As[k][r0]; a[1] = As[k][r0 + 1];
            a[2] = As[k][r0 + 2]; a[3] = As[k][r0 + 3];
            *(float4*)&bb[0] = *(float4*)&Bs[k][j0];
            *(float4*)&bb[4] = *(float4*)&Bs[k][j0 + 4];
#pragma unroll
            for (int i = 0; i < 4; i++)
#pragma unroll
                for (int j = 0; j < 8; j++)
                    acc[i][j] = fmaf(a[i], bb[j], acc[i][j]);
        }
        __syncthreads();
    }
    float bj[8];
    *(float4*)&bj[0] = *(const float4*)(g_bP + b * WIN + j0);
    *(float4*)&bj[4] = *(const float4*)(g_bP + b * WIN + j0 + 4);
#pragma unroll
    for (int i = 0; i < 4; i++) {
        float* pp = g_P + ((size_t)b * T_SEQ + t0 + r0 + i) * WIN + j0;
        *(float4*)pp       = make_float4(acc[i][0] + bj[0], acc[i][1] + bj[1],
                                         acc[i][2] + bj[2], acc[i][3] + bj[3]);
        *(float4*)(pp + 4) = make_float4(acc[i][4] + bj[4], acc[i][5] + bj[5],
                                         acc[i][6] + bj[6], acc[i][7] + bj[7]);
    }
}

// ---------------------------------------------------------------------------
// k3: coefficient-space scan. 1 CTA (128 thr) per batch. C (64x64) register-
// resident: thread (h=tid>>6, idx=tid&63) holds Crow[i]=C[idx][32h+i] and
// Ccol[i]=C[32h+i][idx]. 3 barriers/step; alpha distributed via shfl.
// ---------------------------------------------------------------------------
__global__ __launch_bounds__(128, 1) void scan_kernel()
{
    __shared__ float p_sh[2][WIN];
    __shared__ float part_s[2][WIN];
    __shared__ float part_u[2][WIN];
    __shared__ float cnew[WIN];

    const int b    = blockIdx.x;
    const int tid  = threadIdx.x;
    const int h    = tid >> 6;
    const int idx  = tid & 63;
    const int lane = tid & 31;

    float Crow[32], Ccol[32];
#pragma unroll
    for (int i = 0; i < 32; i++) {
        float v = (32 * h + i == idx) ? 1.f : 0.f;  // C = Identity
        Crow[i] = v;
        Ccol[i] = v;
    }

    if (h == 0) p_sh[0][idx] = g_P[((size_t)b * T_SEQ + WIN) * WIN + idx];
    __syncthreads();

    for (int t = WIN; t < T_SEQ; ++t) {
        const int cur = t & 1, nxt = cur ^ 1;

        float pn = 0.f;
        if (h == 0) {
            int tn = (t + 1 < T_SEQ) ? t + 1 : t;
            pn = g_P[((size_t)b * T_SEQ + tn) * WIN + idx];   // prefetch
        }

        // score partial: rows=idx, k in [32h, 32h+32)
        float s0 = 0.f, s1 = 0.f, s2 = 0.f, s3 = 0.f;
        const float* pc = &p_sh[cur][32 * h];
#pragma unroll
        for (int i = 0; i < 32; i += 4) {
            s0 = fmaf(Crow[i + 0], pc[i + 0], s0);
            s1 = fmaf(Crow[i + 1], pc[i + 1], s1);
            s2 = fmaf(Crow[i + 2], pc[i + 2], s2);
            s3 = fmaf(Crow[i + 3], pc[i + 3], s3);
        }
        part_s[h][idx] = (s0 + s1) + (s2 + s3);
        if (h == 0) p_sh[nxt][idx] = pn;
        __syncthreads();

        // softmax over 64 rows + zero-row (logit 0); redundant per warp.
        // Logits are O(1) -> no max-subtraction needed in fp32.
        float sa = part_s[0][lane]      + part_s[1][lane];
        float sb = part_s[0][lane + 32] + part_s[1][lane + 32];
        float ea = __expf(sa), eb = __expf(sb);
        float ssum = ea + eb;
#pragma unroll
        for (int o = 16; o; o >>= 1) ssum += __shfl_xor_sync(0xffffffffu, ssum, o);
        float inv = 1.f / (ssum + 1.f);
        float av = (h ? eb : ea) * inv;   // alpha of row (h?32:0)+lane

        // update partial: c_new[idx] over rows [32h, 32h+32)
        float u0 = 0.f, u1 = 0.f, u2 = 0.f, u3 = 0.f;
#pragma unroll
        for (int i = 0; i < 32; i += 4) {
            u0 = fmaf(__shfl_sync(0xffffffffu, av, i + 0), Ccol[i + 0], u0);
            u1 = fmaf(__shfl_sync(0xffffffffu, av, i + 1), Ccol[i + 1], u1);
            u2 = fmaf(__shfl_sync(0xffffffffu, av, i + 2), Ccol[i + 2], u2);
            u3 = fmaf(__shfl_sync(0xffffffffu, av, i + 3), Ccol[i + 3], u3);
        }
        part_u[h][idx] = (u0 + u1) + (u2 + u3);
        __syncthreads();

        if (h == 0) {
            float c = part_u[0][idx] + part_u[1][idx];
            cnew[idx] = c;
            g_C[((size_t)b * T_SEQ + t) * WIN + idx] = c;
        }
        __syncthreads();

        // ring overwrite of physical slot t%64
        const int slot = t & (WIN - 1);
        if ((slot >> 5) == h) Ccol[slot & 31] = cnew[idx];
        if (idx == slot) {
#pragma unroll
            for (int i = 0; i < 32; i += 4) {
                float4 v4 = *(const float4*)&cnew[32 * h + i];
                Crow[i + 0] = v4.x; Crow[i + 1] = v4.y;
                Crow[i + 2] = v4.z; Crow[i + 3] = v4.w;
            }
        }
    }
}

// ---------------------------------------------------------------------------
// k4: V[b] = C[b] (2048x64) @ F[b] (64x1024), written to d_out for t>=64.
// Tile 64x64, K=64. grid (32 tblk, 16 dblk, 8 b), 256 threads.
// ---------------------------------------------------------------------------
__global__ __launch_bounds__(256) void v_kernel(
    const float* __restrict__ feat, float* __restrict__ out)
{
    __shared__ float Cst[64][68];   // Cst[j][r] = C[t0+r][j]
    __shared__ float Fs[64][64];    // Fs[j][c]  = F[b][j][d0+c]
    const int b  = blockIdx.z;
    const int t0 = blockIdx.x * 64;
    const int d0 = blockIdx.y * 64;
    const int tid = threadIdx.x;
    const int ty = tid >> 4, tx = tid & 15;
    const int r0 = ty * 4, c0 = tx * 4;

    // load C tile (64x64), transpose into Cst
#pragma unroll
    for (int l = 0; l < 4; l++) {
        int s = tid + l * 256;
        int r = s >> 4, j4 = (s & 15) * 4;
        float4 c = *(const float4*)(g_C + ((size_t)b * T_SEQ + t0 + r) * WIN + j4);
        Cst[j4 + 0][r] = c.x; Cst[j4 + 1][r] = c.y;
        Cst[j4 + 2][r] = c.z; Cst[j4 + 3][r] = c.w;
    }
    // load F tile (64x64)
#pragma unroll
    for (int l = 0; l < 4; l++) {
        int s = tid + l * 256;
        int j = s >> 4, c4 = (s & 15) * 4;
        *(float4*)&Fs[j][c4] =
            *(const float4*)(feat + ((size_t)b * T_SEQ + j) * DMODEL + d0 + c4);
    }
    __syncthreads();

    float acc[4][4];
#pragma unroll
    for (int i = 0; i < 4; i++)
#pragma unroll
        for (int j = 0; j < 4; j++) acc[i][j] = 0.f;

#pragma unroll 8
    for (int k = 0; k < 64; k++) {
        float a[4], bb[4];
        a[0] = Cst[k][r0]; a[1] = Cst[k][r0 + 1];
        a[2] = Cst[k][r0 + 2]; a[3] = Cst[k][r0 + 3];
        *(float4*)&bb[0] = *(float4*)&Fs[k][c0];
#pragma unroll
        for (int i = 0; i < 4; i++)
#pragma unroll
            for (int j = 0; j < 4; j++)
                acc[i][j] = fmaf(a[i], bb[j], acc[i][j]);
    }

#pragma unroll
    for (int i = 0; i < 4; i++) {
        int t = t0 + r0 + i;
        if (t >= WIN) {
            *(float4*)(out + ((size_t)b * T_SEQ + t) * DMODEL + d0 + c0) =
                make_float4(acc[i][0], acc[i][1], acc[i][2], acc[i][3]);
        }
    }
}

// ---------------------------------------------------------------------------
// k5: epilogue y = tanh(v)*f + f, LayerNorm. v from d_out (t>=64) / feature.
// ---------------------------------------------------------------------------
__global__ __launch_bounds__(256) void ln_kernel(
    const float* __restrict__ feature, const float* __restrict__ g,
    const float* __restrict__ bt, float* __restrict__ out)
{
    const int row = blockIdx.x;
    const int t = row & (T_SEQ - 1);
    const float* fp = feature + (size_t)row * DMODEL;
    float* op = out + (size_t)row * DMODEL;
    const float* vp = (t < WIN) ? fp : op;
    const int tid = threadIdx.x;
    const int lane = tid & 31, warp = tid >> 5;

    float4 f = *(const float4*)(fp + tid * 4);
    float4 v = *(const float4*)(vp + tid * 4);
    float y0 = tanhf(v.x) * f.x + f.x;
    float y1 = tanhf(v.y) * f.y + f.y;
    float y2 = tanhf(v.z) * f.z + f.z;
    float y3 = tanhf(v.w) * f.w + f.w;

    float s  = y0 + y1 + y2 + y3;
    float ss = y0 * y0 + y1 * y1 + y2 * y2 + y3 * y3;
#pragma unroll
    for (int o = 16; o > 0; o >>= 1) {
        s  += __shfl_xor_sync(0xffffffffu, s, o);
        ss += __shfl_xor_sync(0xffffffffu, ss, o);
    }
    __shared__ float red[8][2];
    if (lane == 0) { red[warp][0] = s; red[warp][1] = ss; }
    __syncthreads();
    if (warp == 0) {
        float a = (lane < 8) ? red[lane][0] : 0.f;
        float c = (lane < 8) ? red[lane][1] : 0.f;
#pragma unroll
        for (int o = 4; o > 0; o >>= 1) {
            a += __shfl_xor_sync(0xffffffffu, a, o);
            c += __shfl_xor_sync(0xffffffffu, c, o);
        }
        if (lane == 0) { red[0][0] = a; red[0][1] = c; }
    }
    __syncthreads();
    const float mu   = red[0][0] * (1.f / DMODEL);
    const float var  = red[0][1] * (1.f / DMODEL) - mu * mu;
    const float rstd = rsqrtf(var + 1e-5f);

    float4 gg = *(const float4*)(g + tid * 4);
    float4 bb = *(const float4*)(bt + tid * 4);
    float4 o;
    o.x = (y0 - mu) * rstd * gg.x + bb.x;
    o.y = (y1 - mu) * rstd * gg.y + bb.y;
    o.z = (y2 - mu) * rstd * gg.z + bb.z;
    o.w = (y3 - mu) * rstd * gg.w + bb.w;
    *(float4*)(op + tid * 4) = o;
}

// ---------------------------------------------------------------------------
extern "C" void kernel_launch(void* const* d_in, const int* in_sizes, int n_in,
                              void* d_out, int out_size)
{
    const float* feature = (const float*)d_in[0];
    const float* wq_w    = (const float*)d_in[1];
    const float* wq_b    = (const float*)d_in[2];
    const float* w2_w    = (const float*)d_in[3];
    // d_in[4] = w2_b: cancels by softmax shift-invariance
    const float* ln_g    = (const float*)d_in[5];
    const float* ln_b    = (const float*)d_in[6];
    float* out = (float*)d_out;

    bias_p_kernel<<<BATCH, 256>>>(feature, wq_b, w2_w);
    m_kernel<<<dim3(8, BATCH), 256>>>(wq_w, w2_w, feature);
    p_kernel<<<dim3(16, BATCH), 256>>>(feature);
    scan_kernel<<<BATCH, 128>>>();
    v_kernel<<<dim3(32, 16, BATCH), 256>>>(feature, out);
    ln_kernel<<<BATCH * T_SEQ, 256>>>(feature, ln_g, ln_b, out);
}

// round 4
// speedup vs baseline: 3.4191x; 1.2260x over previous
#include <cuda_runtime.h>
#include <cstdint>

#define T_SEQ  2048
#define BATCH  8
#define DMODEL 1024
#define WIN    64

// Scratch (≈10 MB total)
__device__ float g_M[(size_t)BATCH * DMODEL * WIN];   // M[b][d][j]
__device__ float g_P[(size_t)BATCH * T_SEQ * WIN];    // p_t[j] per batch
__device__ float g_C[(size_t)BATCH * T_SEQ * WIN];    // coefficients of v_t
__device__ float g_bP[BATCH * WIN];                   // bias term of p

// packed f32x2 fma
__device__ __forceinline__ void fma2(uint64_t& acc, uint64_t a, uint64_t b) {
    asm("fma.rn.f32x2 %0, %1, %2, %0;" : "+l"(acc) : "l"(a), "l"(b));
}
__device__ __forceinline__ float lo2(uint64_t v) {
    float a; uint32_t l = (uint32_t)v; asm("mov.b32 %0, %1;" : "=f"(a) : "r"(l)); return a;
}
__device__ __forceinline__ float hi2(uint64_t v) {
    float a; uint32_t h = (uint32_t)(v >> 32); asm("mov.b32 %0, %1;" : "=f"(a) : "r"(h)); return a;
}

// ---------------------------------------------------------------------------
// biasP[b][j] = sum_e wq_b[e] * w2[e] * F[b][j][e]
// ---------------------------------------------------------------------------
__global__ __launch_bounds__(256) void bias_p_kernel(
    const float* __restrict__ feat, const float* __restrict__ wqb,
    const float* __restrict__ w2)
{
    const int b = blockIdx.x;
    const int j = threadIdx.x >> 2;
    const int q = threadIdx.x & 3;
    const float* fp = feat + ((size_t)b * T_SEQ + j) * DMODEL + q * 256;
    float s = 0.f;
#pragma unroll 4
    for (int e = 0; e < 256; e += 4) {
        float4 f  = *(const float4*)(fp + e);
        float4 wb = *(const float4*)(wqb + q * 256 + e);
        float4 ww = *(const float4*)(w2 + q * 256 + e);
        s += f.x * wb.x * ww.x + f.y * wb.y * ww.y +
             f.z * wb.z * ww.z + f.w * wb.w * ww.w;
    }
    s += __shfl_xor_sync(0xffffffffu, s, 1);
    s += __shfl_xor_sync(0xffffffffu, s, 2);
    if (q == 0) g_bP[b * WIN + j] = s;
}

// ---------------------------------------------------------------------------
// k1: M[b] = wq @ (F[b,:64]*w2)^T.  Tile 128x64, K=1024.
// ---------------------------------------------------------------------------
__global__ __launch_bounds__(256) void m_kernel(
    const float* __restrict__ wq, const float* __restrict__ w2,
    const float* __restrict__ feat)
{
    __shared__ float As[16][129];
    __shared__ float Bs[16][68];
    const int b  = blockIdx.y;
    const int d0 = blockIdx.x * 128;
    const int tid = threadIdx.x;
    const int ty = tid >> 3, tx = tid & 7;
    const int r0 = ty * 4, j0 = tx * 8;

    float acc[4][8];
#pragma unroll
    for (int i = 0; i < 4; i++)
#pragma unroll
        for (int j = 0; j < 8; j++) acc[i][j] = 0.f;

    for (int e0 = 0; e0 < DMODEL; e0 += 16) {
#pragma unroll
        for (int l = 0; l < 2; l++) {
            int s = tid + l * 256;
            int r = s >> 2, kc = (s & 3) * 4;
            float4 w = *(const float4*)(wq + (size_t)(d0 + r) * DMODEL + e0 + kc);
            As[kc + 0][r] = w.x; As[kc + 1][r] = w.y;
            As[kc + 2][r] = w.z; As[kc + 3][r] = w.w;
        }
        {
            int j = tid >> 2, kc = (tid & 3) * 4;
            float4 f = *(const float4*)(feat + ((size_t)b * T_SEQ + j) * DMODEL + e0 + kc);
            float4 w = *(const float4*)(w2 + e0 + kc);
            Bs[kc + 0][j] = f.x * w.x; Bs[kc + 1][j] = f.y * w.y;
            Bs[kc + 2][j] = f.z * w.z; Bs[kc + 3][j] = f.w * w.w;
        }
        __syncthreads();
#pragma unroll
        for (int k = 0; k < 16; k++) {
            float a[4], bb[8];
            a[0] = As[k][r0]; a[1] = As[k][r0 + 1];
            a[2] = As[k][r0 + 2]; a[3] = As[k][r0 + 3];
            *(float4*)&bb[0] = *(float4*)&Bs[k][j0];
            *(float4*)&bb[4] = *(float4*)&Bs[k][j0 + 4];
#pragma unroll
            for (int i = 0; i < 4; i++)
#pragma unroll
                for (int j = 0; j < 8; j++)
                    acc[i][j] = fmaf(a[i], bb[j], acc[i][j]);
        }
        __syncthreads();
    }
#pragma unroll
    for (int i = 0; i < 4; i++) {
        float* mp = g_M + ((size_t)b * DMODEL + d0 + r0 + i) * WIN + j0;
        *(float4*)mp       = make_float4(acc[i][0], acc[i][1], acc[i][2], acc[i][3]);
        *(float4*)(mp + 4) = make_float4(acc[i][4], acc[i][5], acc[i][6], acc[i][7]);
    }
}

// ---------------------------------------------------------------------------
// k2: P[b] = feature[b] @ M[b] + biasP.  Tile 128x64.
// ---------------------------------------------------------------------------
__global__ __launch_bounds__(256) void p_kernel(const float* __restrict__ feat)
{
    __shared__ float As[16][129];
    __shared__ float Bs[16][68];
    const int b  = blockIdx.y;
    const int t0 = blockIdx.x * 128;
    const int tid = threadIdx.x;
    const int ty = tid >> 3, tx = tid & 7;
    const int r0 = ty * 4, j0 = tx * 8;

    float acc[4][8];
#pragma unroll
    for (int i = 0; i < 4; i++)
#pragma unroll
        for (int j = 0; j < 8; j++) acc[i][j] = 0.f;

    for (int e0 = 0; e0 < DMODEL; e0 += 16) {
#pragma unroll
        for (int l = 0; l < 2; l++) {
            int s = tid + l * 256;
            int r = s >> 2, kc = (s & 3) * 4;
            float4 w = *(const float4*)(feat + ((size_t)b * T_SEQ + t0 + r) * DMODEL + e0 + kc);
            As[kc + 0][r] = w.x; As[kc + 1][r] = w.y;
            As[kc + 2][r] = w.z; As[kc + 3][r] = w.w;
        }
        {
            int k = tid >> 4, j4 = (tid & 15) * 4;
            *(float4*)&Bs[k][j4] =
                *(const float4*)(g_M + ((size_t)b * DMODEL + e0 + k) * WIN + j4);
        }
        __syncthreads();
#pragma unroll
        for (int k = 0; k < 16; k++) {
            float a[4], bb[8];
            a[0] = As[k][r0]; a[1] = As[k][r0 + 1];
            a[2] = As[k][r0 + 2]; a[3] = As[k][r0 + 3];
            *(float4*)&bb[0] = *(float4*)&Bs[k][j0];
            *(float4*)&bb[4] = *(float4*)&Bs[k][j0 + 4];
#pragma unroll
            for (int i = 0; i < 4; i++)
#pragma unroll
                for (int j = 0; j < 8; j++)
                    acc[i][j] = fmaf(a[i], bb[j], acc[i][j]);
        }
        __syncthreads();
    }
    float bj[8];
    *(float4*)&bj[0] = *(const float4*)(g_bP + b * WIN + j0);
    *(float4*)&bj[4] = *(const float4*)(g_bP + b * WIN + j0 + 4);
#pragma unroll
    for (int i = 0; i < 4; i++) {
        float* pp = g_P + ((size_t)b * T_SEQ + t0 + r0 + i) * WIN + j0;
        *(float4*)pp       = make_float4(acc[i][0] + bj[0], acc[i][1] + bj[1],
                                         acc[i][2] + bj[2], acc[i][3] + bj[3]);
        *(float4*)(pp + 4) = make_float4(acc[i][4] + bj[4], acc[i][5] + bj[5],
                                         acc[i][6] + bj[6], acc[i][7] + bj[7]);
    }
}

// ---------------------------------------------------------------------------
// k3: coefficient-space scan, deferred normalization.
// 64 threads per batch. Thread i owns: row i of C in registers (32 f32x2),
// column i of C in smem (Ccs, LDS-indexed ring). Per step:
//   A: s_i = Crow_i . p   -> e_i = exp(s_i) -> e_sh     [bar]
//   B: (u_j, d) = sum_r e_r * (C[r][j], 1)  (packed fma2, d off critical path)
//      c_j = u_j * rcp(d+1); ring: Ccs[j][slot]=c_j; thread slot reloads row.
//   [bar]
// ---------------------------------------------------------------------------
__global__ __launch_bounds__(64, 1) void scan_kernel()
{
    __shared__ __align__(16) float p_sh[2][WIN];
    __shared__ __align__(16) float e_sh[WIN];
    __shared__ __align__(16) float cnew_sh[WIN];
    __shared__ __align__(16) float Ccs[WIN][66];   // Ccs[j][r] = C[r][j]

    const int b   = blockIdx.x;
    const int tid = threadIdx.x;       // 0..63 = row AND column index

    // C = Identity
    uint64_t CrowP[32];
#pragma unroll
    for (int k = 0; k < 32; k++) {
        float x0 = (2 * k     == tid) ? 1.f : 0.f;
        float x1 = (2 * k + 1 == tid) ? 1.f : 0.f;
        CrowP[k] = ((uint64_t)__float_as_uint(x1) << 32) | __float_as_uint(x0);
    }
    for (int r = 0; r < WIN; r++) Ccs[tid][r] = (r == tid) ? 1.f : 0.f;

    const uint64_t ones = 0x3F8000003F800000ull;  // (1.0f, 1.0f)

    p_sh[WIN & 1][tid] = g_P[((size_t)b * T_SEQ + WIN) * WIN + tid];
    __syncthreads();

    for (int t = WIN; t < T_SEQ; ++t) {
        const int cur = t & 1, nxt = cur ^ 1;

        // prefetch next p (L2-resident)
        const int tn = (t + 1 < T_SEQ) ? t + 1 : t;
        const float pn = g_P[((size_t)b * T_SEQ + tn) * WIN + tid];

        // phase A: score for own row
        uint64_t s2 = 0;
        const uint64_t* pc = (const uint64_t*)&p_sh[cur][0];
#pragma unroll
        for (int k = 0; k < 32; k++) fma2(s2, CrowP[k], pc[k]);
        const float e = __expf(lo2(s2) + hi2(s2));
        e_sh[tid] = e;
        p_sh[nxt][tid] = pn;
        __syncthreads();

        // phase B: unnormalized update + denominator, packed
        uint64_t u2 = 0, d2 = 0;
        const uint64_t* ec = (const uint64_t*)&e_sh[0];
        const uint64_t* cc = (const uint64_t*)&Ccs[tid][0];
#pragma unroll
        for (int r = 0; r < 32; r++) {
            const uint64_t ev = ec[r];
            fma2(u2, ev, cc[r]);
            fma2(d2, ev, ones);
        }
        const float inv = __fdividef(1.f, lo2(d2) + hi2(d2) + 1.f);
        const float c   = (lo2(u2) + hi2(u2)) * inv;

        g_C[((size_t)b * T_SEQ + t) * WIN + tid] = c;
        cnew_sh[tid] = c;
        const int slot = t & (WIN - 1);
        Ccs[tid][slot] = c;            // own column, thread-private
        __syncthreads();

        // ring: thread 'slot' replaces its register row with c_new
        if (tid == slot) {
            const uint64_t* cn = (const uint64_t*)&cnew_sh[0];
#pragma unroll
            for (int k = 0; k < 32; k++) CrowP[k] = cn[k];
        }
    }
}

// ---------------------------------------------------------------------------
// k4: V[b] = C[b] (2048x64) @ F[b] (64x1024) -> d_out for t>=64.
// ---------------------------------------------------------------------------
__global__ __launch_bounds__(256) void v_kernel(
    const float* __restrict__ feat, float* __restrict__ out)
{
    __shared__ float Cst[64][68];
    __shared__ float Fs[64][64];
    const int b  = blockIdx.z;
    const int t0 = blockIdx.x * 64;
    const int d0 = blockIdx.y * 64;
    const int tid = threadIdx.x;
    const int ty = tid >> 4, tx = tid & 15;
    const int r0 = ty * 4, c0 = tx * 4;

#pragma unroll
    for (int l = 0; l < 4; l++) {
        int s = tid + l * 256;
        int r = s >> 4, j4 = (s & 15) * 4;
        float4 c = *(const float4*)(g_C + ((size_t)b * T_SEQ + t0 + r) * WIN + j4);
        Cst[j4 + 0][r] = c.x; Cst[j4 + 1][r] = c.y;
        Cst[j4 + 2][r] = c.z; Cst[j4 + 3][r] = c.w;
    }
#pragma unroll
    for (int l = 0; l < 4; l++) {
        int s = tid + l * 256;
        int j = s >> 4, c4 = (s & 15) * 4;
        *(float4*)&Fs[j][c4] =
            *(const float4*)(feat + ((size_t)b * T_SEQ + j) * DMODEL + d0 + c4);
    }
    __syncthreads();

    float acc[4][4];
#pragma unroll
    for (int i = 0; i < 4; i++)
#pragma unroll
        for (int j = 0; j < 4; j++) acc[i][j] = 0.f;

#pragma unroll 8
    for (int k = 0; k < 64; k++) {
        float a[4], bb[4];
        a[0] = Cst[k][r0]; a[1] = Cst[k][r0 + 1];
        a[2] = Cst[k][r0 + 2]; a[3] = Cst[k][r0 + 3];
        *(float4*)&bb[0] = *(float4*)&Fs[k][c0];
#pragma unroll
        for (int i = 0; i < 4; i++)
#pragma unroll
            for (int j = 0; j < 4; j++)
                acc[i][j] = fmaf(a[i], bb[j], acc[i][j]);
    }

#pragma unroll
    for (int i = 0; i < 4; i++) {
        int t = t0 + r0 + i;
        if (t >= WIN) {
            *(float4*)(out + ((size_t)b * T_SEQ + t) * DMODEL + d0 + c0) =
                make_float4(acc[i][0], acc[i][1], acc[i][2], acc[i][3]);
        }
    }
}

// ---------------------------------------------------------------------------
// k5: epilogue y = tanh(v)*f + f, LayerNorm.
// ---------------------------------------------------------------------------
__global__ __launch_bounds__(256) void ln_kernel(
    const float* __restrict__ feature, const float* __restrict__ g,
    const float* __restrict__ bt, float* __restrict__ out)
{
    const int row = blockIdx.x;
    const int t = row & (T_SEQ - 1);
    const float* fp = feature + (size_t)row * DMODEL;
    float* op = out + (size_t)row * DMODEL;
    const float* vp = (t < WIN) ? fp : op;
    const int tid = threadIdx.x;
    const int lane = tid & 31, warp = tid >> 5;

    float4 f = *(const float4*)(fp + tid * 4);
    float4 v = *(const float4*)(vp + tid * 4);
    float y0 = tanhf(v.x) * f.x + f.x;
    float y1 = tanhf(v.y) * f.y + f.y;
    float y2 = tanhf(v.z) * f.z + f.z;
    float y3 = tanhf(v.w) * f.w + f.w;

    float s  = y0 + y1 + y2 + y3;
    float ss = y0 * y0 + y1 * y1 + y2 * y2 + y3 * y3;
#pragma unroll
    for (int o = 16; o > 0; o >>= 1) {
        s  += __shfl_xor_sync(0xffffffffu, s, o);
        ss += __shfl_xor_sync(0xffffffffu, ss, o);
    }
    __shared__ float red[8][2];
    if (lane == 0) { red[warp][0] = s; red[warp][1] = ss; }
    __syncthreads();
    if (warp == 0) {
        float a = (lane < 8) ? red[lane][0] : 0.f;
        float c = (lane < 8) ? red[lane][1] : 0.f;
#pragma unroll
        for (int o = 4; o > 0; o >>= 1) {
            a += __shfl_xor_sync(0xffffffffu, a, o);
            c += __shfl_xor_sync(0xffffffffu, c, o);
        }
        if (lane == 0) { red[0][0] = a; red[0][1] = c; }
    }
    __syncthreads();
    const float mu   = red[0][0] * (1.f / DMODEL);
    const float var  = red[0][1] * (1.f / DMODEL) - mu * mu;
    const float rstd = rsqrtf(var + 1e-5f);

    float4 gg = *(const float4*)(g + tid * 4);
    float4 bb = *(const float4*)(bt + tid * 4);
    float4 o;
    o.x = (y0 - mu) * rstd * gg.x + bb.x;
    o.y = (y1 - mu) * rstd * gg.y + bb.y;
    o.z = (y2 - mu) * rstd * gg.z + bb.z;
    o.w = (y3 - mu) * rstd * gg.w + bb.w;
    *(float4*)(op + tid * 4) = o;
}

// ---------------------------------------------------------------------------
extern "C" void kernel_launch(void* const* d_in, const int* in_sizes, int n_in,
                              void* d_out, int out_size)
{
    const float* feature = (const float*)d_in[0];
    const float* wq_w    = (const float*)d_in[1];
    const float* wq_b    = (const float*)d_in[2];
    const float* w2_w    = (const float*)d_in[3];
    // d_in[4] = w2_b: cancels by softmax shift-invariance
    const float* ln_g    = (const float*)d_in[5];
    const float* ln_b    = (const float*)d_in[6];
    float* out = (float*)d_out;

    bias_p_kernel<<<BATCH, 256>>>(feature, wq_b, w2_w);
    m_kernel<<<dim3(8, BATCH), 256>>>(wq_w, w2_w, feature);
    p_kernel<<<dim3(16, BATCH), 256>>>(feature);
    scan_kernel<<<BATCH, 64>>>();
    v_kernel<<<dim3(32, 16, BATCH), 256>>>(feature, out);
    ln_kernel<<<BATCH * T_SEQ, 256>>>(feature, ln_g, ln_b, out);
}